// round 10
// baseline (speedup 1.0000x reference)
#include <cuda_runtime.h>
#include <cstdint>

#define D 128
#define TM 64
#define THREADS 256
#define AROW 132                        // floats per k-row of dup'd activation tile (128 dup + 4 pad)
#define SA_F (128 * AROW)               // one k-half, duplicated: 16896 floats
#define SW_F (256 * 128)                // full W1
#define SMEM_BYTES ((SA_F + SW_F) * 4)  // 198,656 B

#define NN_MAX 50048
#define E_MAX  600064

// CSR scratch (static __device__ per allocation rules)
__device__ int d_cnt[NN_MAX];
__device__ int d_off[NN_MAX + 1];
__device__ int d_cur[NN_MAX];
__device__ int d_sorted[E_MAX];

// ---------------------------------------------------------------------------
__global__ void zero_cnt_kernel(int n) {
    int i = blockIdx.x * blockDim.x + threadIdx.x;
    if (i < n) d_cnt[i] = 0;
}

__global__ void hist_kernel(const int* __restrict__ recv, int E) {
    int e = blockIdx.x * blockDim.x + threadIdx.x;
    if (e < E) atomicAdd(&d_cnt[recv[e]], 1);
}

// Single-CTA exclusive scan over n counters -> d_off (and copy to d_cur).
__global__ __launch_bounds__(1024)
void scan_kernel(int n, int E) {
    __shared__ int wsum[32];
    const int t = threadIdx.x;
    const int lane = t & 31, w = t >> 5;
    const int chunk = (n + 1023) >> 10;
    const int lo = t * chunk;
    const int hi = min(n, lo + chunk);

    int s = 0;
    for (int i = lo; i < hi; i++) s += d_cnt[i];

    // inclusive warp scan of per-thread sums
    int v = s;
    #pragma unroll
    for (int dlt = 1; dlt < 32; dlt <<= 1) {
        int u = __shfl_up_sync(0xFFFFFFFFu, v, dlt);
        if (lane >= dlt) v += u;
    }
    if (lane == 31) wsum[w] = v;
    __syncthreads();
    if (w == 0) {
        int z = wsum[lane];
        #pragma unroll
        for (int dlt = 1; dlt < 32; dlt <<= 1) {
            int u = __shfl_up_sync(0xFFFFFFFFu, z, dlt);
            if (lane >= dlt) z += u;
        }
        wsum[lane] = z;
    }
    __syncthreads();

    int excl = v - s + (w > 0 ? wsum[w - 1] : 0);
    int run = excl;
    for (int i = lo; i < hi; i++) {
        d_off[i] = run;
        d_cur[i] = run;
        run += d_cnt[i];
    }
    if (t == 1023) d_off[n] = E;
}

__global__ void fill_kernel(const int* __restrict__ recv, int E) {
    int e = blockIdx.x * blockDim.x + threadIdx.x;
    if (e < E) {
        int pos = atomicAdd(&d_cur[recv[e]], 1);
        d_sorted[pos] = e;
    }
}

// ---------------------------------------------------------------------------
// Packed-f32x2 helpers (sm_100+). Exact fp32 math, 2 FMAs per instruction.
__device__ __forceinline__ void fma2(unsigned long long& d,
                                     unsigned long long a, unsigned long long b) {
    asm("fma.rn.f32x2 %0, %1, %2, %0;" : "+l"(d) : "l"(a), "l"(b));
}
__device__ __forceinline__ float2 unpk(unsigned long long p) {
    float2 r;
    asm("mov.b64 {%0, %1}, %2;" : "=f"(r.x), "=f"(r.y) : "l"(p));
    return r;
}
__device__ __forceinline__ unsigned long long pk(float lo, float hi) {
    unsigned long long p;
    asm("mov.b64 %0, {%1, %2};" : "=l"(p) : "f"(lo), "f"(hi));
    return p;
}

// ---------------------------------------------------------------------------
// Fused gather + MLP. Phase 0 k-half = x; phase 1 k-half = CSR gather-sum of
// edge_attr rows (no atomics, no g_agg). GEMMs: packed f32x2 as in R5.
__global__ __launch_bounds__(THREADS, 1)
void mlp_kernel(const float* __restrict__ x,
                const float* __restrict__ edge_attr,
                const float* __restrict__ W1, const float* __restrict__ b1,
                const float* __restrict__ W2, const float* __restrict__ b2,
                float* __restrict__ out, int nNodes) {
    extern __shared__ float smem[];
    float* sA = smem;            // [128][AROW] dup'd activations (reused for hidden)
    float* sW = smem + SA_F;     // weights

    const int tid  = threadIdx.x;
    const int lane = tid & 31;
    const int warp = tid >> 5;
    const int wc   = warp * 16;            // warp's output-column base
    const int base = blockIdx.x * TM;
    const int n0   = 2 * lane;             // thread's two tile-local nodes (GEMM view)

    // ---- load full W1 (256x128) into sW, coalesced float4 ----
    {
        const float4* src = reinterpret_cast<const float4*>(W1);
        float4* dst = reinterpret_cast<float4*>(sW);
        #pragma unroll
        for (int i = tid; i < SW_F / 4; i += THREADS) dst[i] = src[i];
    }

    unsigned long long acc[2][8];
    #pragma unroll
    for (int a = 0; a < 2; a++)
        #pragma unroll
        for (int c = 0; c < 8; c++) acc[a][c] = 0ull;

    // ================= phase 0 : x half =================
    for (int i = tid; i < TM * 32; i += THREADS) {
        int n  = i & 63;
        int k4 = i >> 6;
        int node = base + n;
        float4 v = {0.f, 0.f, 0.f, 0.f};
        if (node < nNodes)
            v = reinterpret_cast<const float4*>(x + (size_t)node * D)[k4];
        *(unsigned long long*)(sA + (4 * k4 + 0) * AROW + 2 * n) = pk(v.x, v.x);
        *(unsigned long long*)(sA + (4 * k4 + 1) * AROW + 2 * n) = pk(v.y, v.y);
        *(unsigned long long*)(sA + (4 * k4 + 2) * AROW + 2 * n) = pk(v.z, v.z);
        *(unsigned long long*)(sA + (4 * k4 + 3) * AROW + 2 * n) = pk(v.w, v.w);
    }
    __syncthreads();

    {
        const float* wbase = sW + wc;
        #pragma unroll 8
        for (int k = 0; k < 128; k++) {
            ulonglong2 av = *reinterpret_cast<const ulonglong2*>(sA + k * AROW + 4 * lane);
            const ulonglong2* wp = reinterpret_cast<const ulonglong2*>(wbase + k * 128);
            ulonglong2 wA = wp[0], wB = wp[1], wC = wp[2], wE = wp[3];
            fma2(acc[0][0], av.x, wA.x); fma2(acc[0][1], av.x, wA.y);
            fma2(acc[0][2], av.x, wB.x); fma2(acc[0][3], av.x, wB.y);
            fma2(acc[0][4], av.x, wC.x); fma2(acc[0][5], av.x, wC.y);
            fma2(acc[0][6], av.x, wE.x); fma2(acc[0][7], av.x, wE.y);
            fma2(acc[1][0], av.y, wA.x); fma2(acc[1][1], av.y, wA.y);
            fma2(acc[1][2], av.y, wB.x); fma2(acc[1][3], av.y, wB.y);
            fma2(acc[1][4], av.y, wC.x); fma2(acc[1][5], av.y, wC.y);
            fma2(acc[1][6], av.y, wE.x); fma2(acc[1][7], av.y, wE.y);
        }
    }
    __syncthreads();   // phase-0 reads of sA done everywhere

    // ================= phase 1 : CSR gather-sum of edge_attr =================
    // Warp w aggregates tile-nodes [8w, 8w+8). One LDG.128 per warp = one full
    // 512B edge row; unrolled x4 -> 2KB in flight per warp (DRAM-bw sustaining).
    {
        const float4* E4 = reinterpret_cast<const float4*>(edge_attr);
        #pragma unroll
        for (int q = 0; q < 8; q++) {
            int n = warp * 8 + q;
            int node = base + n;
            float4 a = {0.f, 0.f, 0.f, 0.f};
            if (node < nNodes) {
                int s = d_off[node];
                int t = d_off[node + 1];
                int j = s;
                for (; j + 4 <= t; j += 4) {
                    int e0 = d_sorted[j],     e1 = d_sorted[j + 1];
                    int e2 = d_sorted[j + 2], e3 = d_sorted[j + 3];
                    float4 a0 = E4[(size_t)e0 * 32 + lane];
                    float4 a1 = E4[(size_t)e1 * 32 + lane];
                    float4 a2 = E4[(size_t)e2 * 32 + lane];
                    float4 a3 = E4[(size_t)e3 * 32 + lane];
                    a.x += (a0.x + a1.x) + (a2.x + a3.x);
                    a.y += (a0.y + a1.y) + (a2.y + a3.y);
                    a.z += (a0.z + a1.z) + (a2.z + a3.z);
                    a.w += (a0.w + a1.w) + (a2.w + a3.w);
                }
                for (; j < t; j++) {
                    float4 a0 = E4[(size_t)d_sorted[j] * 32 + lane];
                    a.x += a0.x; a.y += a0.y; a.z += a0.z; a.w += a0.w;
                }
            }
            // dup-store into sA rows 4*lane..4*lane+3, column pair 2n
            *(unsigned long long*)(sA + (4 * lane + 0) * AROW + 2 * n) = pk(a.x, a.x);
            *(unsigned long long*)(sA + (4 * lane + 1) * AROW + 2 * n) = pk(a.y, a.y);
            *(unsigned long long*)(sA + (4 * lane + 2) * AROW + 2 * n) = pk(a.z, a.z);
            *(unsigned long long*)(sA + (4 * lane + 3) * AROW + 2 * n) = pk(a.w, a.w);
        }
    }
    __syncthreads();

    {
        const float* wbase = sW + 128 * 128 + wc;
        #pragma unroll 8
        for (int k = 0; k < 128; k++) {
            ulonglong2 av = *reinterpret_cast<const ulonglong2*>(sA + k * AROW + 4 * lane);
            const ulonglong2* wp = reinterpret_cast<const ulonglong2*>(wbase + k * 128);
            ulonglong2 wA = wp[0], wB = wp[1], wC = wp[2], wE = wp[3];
            fma2(acc[0][0], av.x, wA.x); fma2(acc[0][1], av.x, wA.y);
            fma2(acc[0][2], av.x, wB.x); fma2(acc[0][3], av.x, wB.y);
            fma2(acc[0][4], av.x, wC.x); fma2(acc[0][5], av.x, wC.y);
            fma2(acc[0][6], av.x, wE.x); fma2(acc[0][7], av.x, wE.y);
            fma2(acc[1][0], av.y, wA.x); fma2(acc[1][1], av.y, wA.y);
            fma2(acc[1][2], av.y, wB.x); fma2(acc[1][3], av.y, wB.y);
            fma2(acc[1][4], av.y, wC.x); fma2(acc[1][5], av.y, wC.y);
            fma2(acc[1][6], av.y, wE.x); fma2(acc[1][7], av.y, wE.y);
        }
    }
    __syncthreads();   // GEMM1 reads of sA and sW complete everywhere

    // ---- bias + relu; write hidden (duplicated) back into sA; load W2 ----
    #pragma unroll
    for (int cp = 0; cp < 8; cp++) {
        int c0 = wc + 2 * cp, c1 = c0 + 1;
        float2 h0 = unpk(acc[0][cp]);      // node n0 : cols (c0, c1)
        float2 h1 = unpk(acc[1][cp]);      // node n0+1
        float bc0 = b1[c0], bc1 = b1[c1];
        float v00 = fmaxf(h0.x + bc0, 0.f), v01 = fmaxf(h0.y + bc1, 0.f);
        float v10 = fmaxf(h1.x + bc0, 0.f), v11 = fmaxf(h1.y + bc1, 0.f);
        *(unsigned long long*)(sA + c0 * AROW + 4 * lane)     = pk(v00, v00);
        *(unsigned long long*)(sA + c0 * AROW + 4 * lane + 2) = pk(v10, v10);
        *(unsigned long long*)(sA + c1 * AROW + 4 * lane)     = pk(v01, v01);
        *(unsigned long long*)(sA + c1 * AROW + 4 * lane + 2) = pk(v11, v11);
    }
    {
        const float4* src = reinterpret_cast<const float4*>(W2);
        float4* dst = reinterpret_cast<float4*>(sW);
        #pragma unroll
        for (int i = tid; i < (128 * 128) / 4; i += THREADS) dst[i] = src[i];
    }
    __syncthreads();

    // ---- GEMM2: out = H @ W2 + b2 ----
    #pragma unroll
    for (int a = 0; a < 2; a++)
        #pragma unroll
        for (int c = 0; c < 8; c++) acc[a][c] = 0ull;

    #pragma unroll 8
    for (int k = 0; k < 128; k++) {
        ulonglong2 av = *reinterpret_cast<const ulonglong2*>(sA + k * AROW + 4 * lane);
        const ulonglong2* wp = reinterpret_cast<const ulonglong2*>(sW + k * 128 + wc);
        ulonglong2 wA = wp[0], wB = wp[1], wC = wp[2], wE = wp[3];
        fma2(acc[0][0], av.x, wA.x); fma2(acc[0][1], av.x, wA.y);
        fma2(acc[0][2], av.x, wB.x); fma2(acc[0][3], av.x, wB.y);
        fma2(acc[0][4], av.x, wC.x); fma2(acc[0][5], av.x, wC.y);
        fma2(acc[0][6], av.x, wE.x); fma2(acc[0][7], av.x, wE.y);
        fma2(acc[1][0], av.y, wA.x); fma2(acc[1][1], av.y, wA.y);
        fma2(acc[1][2], av.y, wB.x); fma2(acc[1][3], av.y, wB.y);
        fma2(acc[1][4], av.y, wC.x); fma2(acc[1][5], av.y, wC.y);
        fma2(acc[1][6], av.y, wE.x); fma2(acc[1][7], av.y, wE.y);
    }

    // ---- bias + store ----
    float o[2][16];
    #pragma unroll
    for (int cp = 0; cp < 8; cp++) {
        int c0 = wc + 2 * cp, c1 = c0 + 1;
        float2 p0 = unpk(acc[0][cp]);
        float2 p1 = unpk(acc[1][cp]);
        float bc0 = b2[c0], bc1 = b2[c1];
        o[0][2 * cp]     = p0.x + bc0;
        o[0][2 * cp + 1] = p0.y + bc1;
        o[1][2 * cp]     = p1.x + bc0;
        o[1][2 * cp + 1] = p1.y + bc1;
    }
    #pragma unroll
    for (int q = 0; q < 2; q++) {
        int node = base + n0 + q;
        if (node < nNodes) {
            float* dst = out + (size_t)node * D + wc;
            #pragma unroll
            for (int t = 0; t < 4; t++) {
                float4 v = make_float4(o[q][4 * t], o[q][4 * t + 1],
                                       o[q][4 * t + 2], o[q][4 * t + 3]);
                *reinterpret_cast<float4*>(dst + 4 * t) = v;
            }
        }
    }
}

// ---------------------------------------------------------------------------
extern "C" void kernel_launch(void* const* d_in, const int* in_sizes, int n_in,
                              void* d_out, int out_size) {
    const float* x         = (const float*)d_in[0];
    const float* edge_attr = (const float*)d_in[1];
    const int*   recv      = (const int*)d_in[2];
    const float* W1        = (const float*)d_in[3];
    const float* b1        = (const float*)d_in[4];
    const float* W2        = (const float*)d_in[5];
    const float* b2        = (const float*)d_in[6];
    float* out = (float*)d_out;

    int nNodes = in_sizes[0] / D;
    int E      = in_sizes[2];

    cudaFuncSetAttribute(mlp_kernel, cudaFuncAttributeMaxDynamicSharedMemorySize,
                         SMEM_BYTES);

    // CSR build (no 512B atomics anywhere)
    zero_cnt_kernel<<<(nNodes + 255) / 256, 256>>>(nNodes);
    hist_kernel<<<(E + 255) / 256, 256>>>(recv, E);
    scan_kernel<<<1, 1024>>>(nNodes, E);
    fill_kernel<<<(E + 255) / 256, 256>>>(recv, E);

    // fused gather + MLP
    int tiles = (nNodes + TM - 1) / TM;
    mlp_kernel<<<tiles, THREADS, SMEM_BYTES>>>(x, edge_attr, W1, b1, W2, b2,
                                               out, nNodes);
}

// round 14
// speedup vs baseline: 1.1955x; 1.1955x over previous
#include <cuda_runtime.h>
#include <cstdint>

#define D 128
#define TM 64
#define THREADS 256
#define AROW 132                        // floats per k-row of dup'd activation tile (128 dup + 4 pad)
#define SA_F (128 * AROW)               // one k-half, duplicated: 16896 floats
#define SW_F (256 * 128)                // full W1
#define SMEM_BYTES ((SA_F + SW_F) * 4)  // 198,656 B

#define NN_MAX 50048
#define E_MAX  600064

// CSR + aggregate scratch (static __device__ per allocation rules)
__device__ int   d_cnt[NN_MAX];
__device__ int   d_off[NN_MAX + 1];
__device__ int   d_cur[NN_MAX];
__device__ int   d_sorted[E_MAX];
__device__ float g_agg[NN_MAX * D];

// ---------------------------------------------------------------------------
__global__ void zero_cnt_kernel(int n) {
    int i = blockIdx.x * blockDim.x + threadIdx.x;
    if (i < n) d_cnt[i] = 0;
}

__global__ void hist_kernel(const int* __restrict__ recv, int E) {
    int e = blockIdx.x * blockDim.x + threadIdx.x;
    if (e < E) atomicAdd(&d_cnt[recv[e]], 1);
}

// Single-CTA exclusive scan over n counters -> d_off (and copy to d_cur).
__global__ __launch_bounds__(1024)
void scan_kernel(int n, int E) {
    __shared__ int wsum[32];
    const int t = threadIdx.x;
    const int lane = t & 31, w = t >> 5;
    const int chunk = (n + 1023) >> 10;
    const int lo = t * chunk;
    const int hi = min(n, lo + chunk);

    int s = 0;
    for (int i = lo; i < hi; i++) s += d_cnt[i];

    int v = s;
    #pragma unroll
    for (int dlt = 1; dlt < 32; dlt <<= 1) {
        int u = __shfl_up_sync(0xFFFFFFFFu, v, dlt);
        if (lane >= dlt) v += u;
    }
    if (lane == 31) wsum[w] = v;
    __syncthreads();
    if (w == 0) {
        int z = wsum[lane];
        #pragma unroll
        for (int dlt = 1; dlt < 32; dlt <<= 1) {
            int u = __shfl_up_sync(0xFFFFFFFFu, z, dlt);
            if (lane >= dlt) z += u;
        }
        wsum[lane] = z;
    }
    __syncthreads();

    int excl = v - s + (w > 0 ? wsum[w - 1] : 0);
    int run = excl;
    for (int i = lo; i < hi; i++) {
        d_off[i] = run;
        d_cur[i] = run;
        run += d_cnt[i];
    }
    if (t == 1023) d_off[n] = E;
}

__global__ void fill_kernel(const int* __restrict__ recv, int E) {
    int e = blockIdx.x * blockDim.x + threadIdx.x;
    if (e < E) {
        int pos = atomicAdd(&d_cur[recv[e]], 1);
        d_sorted[pos] = e;
    }
}

// ---------------------------------------------------------------------------
// Gather-reduce: ONE WARP PER NODE, high occupancy. Lanes jointly read full
// 512B edge rows (one coalesced LDG.128 per edge per lane-16B), x4 unrolled
// -> MLP>=4 per warp with 32+ warps/SM resident: DRAM-bandwidth bound.
// Writes every node (zeros included) so no zero_agg pass is needed.
__global__ __launch_bounds__(256)
void gather_kernel(const float* __restrict__ edge_attr, int nNodes) {
    const int lane = threadIdx.x & 31;
    const int node = (blockIdx.x * blockDim.x + threadIdx.x) >> 5;
    if (node >= nNodes) return;

    const float4* E4 = reinterpret_cast<const float4*>(edge_attr);
    float4 a = {0.f, 0.f, 0.f, 0.f};
    int s = d_off[node];
    int t = d_off[node + 1];
    int j = s;
    for (; j + 4 <= t; j += 4) {
        int e0 = d_sorted[j],     e1 = d_sorted[j + 1];
        int e2 = d_sorted[j + 2], e3 = d_sorted[j + 3];
        float4 a0 = E4[(size_t)e0 * 32 + lane];
        float4 a1 = E4[(size_t)e1 * 32 + lane];
        float4 a2 = E4[(size_t)e2 * 32 + lane];
        float4 a3 = E4[(size_t)e3 * 32 + lane];
        a.x += (a0.x + a1.x) + (a2.x + a3.x);
        a.y += (a0.y + a1.y) + (a2.y + a3.y);
        a.z += (a0.z + a1.z) + (a2.z + a3.z);
        a.w += (a0.w + a1.w) + (a2.w + a3.w);
    }
    for (; j < t; j++) {
        float4 a0 = E4[(size_t)d_sorted[j] * 32 + lane];
        a.x += a0.x; a.y += a0.y; a.z += a0.z; a.w += a0.w;
    }
    reinterpret_cast<float4*>(g_agg + (size_t)node * D)[lane] = a;
}

// ---------------------------------------------------------------------------
// Packed-f32x2 helpers (sm_100+). Exact fp32 math, 2 FMAs per instruction.
__device__ __forceinline__ void fma2(unsigned long long& d,
                                     unsigned long long a, unsigned long long b) {
    asm("fma.rn.f32x2 %0, %1, %2, %0;" : "+l"(d) : "l"(a), "l"(b));
}
__device__ __forceinline__ float2 unpk(unsigned long long p) {
    float2 r;
    asm("mov.b64 {%0, %1}, %2;" : "=f"(r.x), "=f"(r.y) : "l"(p));
    return r;
}
__device__ __forceinline__ unsigned long long pk(float lo, float hi) {
    unsigned long long p;
    asm("mov.b64 %0, {%1, %2};" : "=l"(p) : "f"(lo), "f"(hi));
    return p;
}

// ---------------------------------------------------------------------------
// Fused MLP, packed-f32x2 (identical to the 243.7us R5 version).
__global__ __launch_bounds__(THREADS, 1)
void mlp_kernel(const float* __restrict__ x,
                const float* __restrict__ W1, const float* __restrict__ b1,
                const float* __restrict__ W2, const float* __restrict__ b2,
                float* __restrict__ out, int nNodes) {
    extern __shared__ float smem[];
    float* sA = smem;            // [128][AROW] dup'd activations (reused for hidden)
    float* sW = smem + SA_F;     // weights

    const int tid  = threadIdx.x;
    const int lane = tid & 31;
    const int warp = tid >> 5;
    const int wc   = warp * 16;            // warp's output-column base
    const int base = blockIdx.x * TM;
    const int n0   = 2 * lane;             // thread's two tile-local nodes

    {
        const float4* src = reinterpret_cast<const float4*>(W1);
        float4* dst = reinterpret_cast<float4*>(sW);
        #pragma unroll
        for (int i = tid; i < SW_F / 4; i += THREADS) dst[i] = src[i];
    }

    unsigned long long acc[2][8];
    #pragma unroll
    for (int a = 0; a < 2; a++)
        #pragma unroll
        for (int c = 0; c < 8; c++) acc[a][c] = 0ull;

    // ---- GEMM1 in two k-phases: K 0..127 = x, K 128..255 = g_agg ----
    for (int phase = 0; phase < 2; phase++) {
        const float* src = (phase == 0) ? x : g_agg;
        if (phase == 1) __syncthreads();

        for (int i = tid; i < TM * 32; i += THREADS) {
            int n  = i & 63;
            int k4 = i >> 6;
            int node = base + n;
            float4 v = {0.f, 0.f, 0.f, 0.f};
            if (node < nNodes)
                v = reinterpret_cast<const float4*>(src + (size_t)node * D)[k4];
            *(unsigned long long*)(sA + (4 * k4 + 0) * AROW + 2 * n) = pk(v.x, v.x);
            *(unsigned long long*)(sA + (4 * k4 + 1) * AROW + 2 * n) = pk(v.y, v.y);
            *(unsigned long long*)(sA + (4 * k4 + 2) * AROW + 2 * n) = pk(v.z, v.z);
            *(unsigned long long*)(sA + (4 * k4 + 3) * AROW + 2 * n) = pk(v.w, v.w);
        }
        __syncthreads();

        const float* wbase = sW + phase * 128 * 128 + wc;
        #pragma unroll 8
        for (int k = 0; k < 128; k++) {
            ulonglong2 av = *reinterpret_cast<const ulonglong2*>(sA + k * AROW + 4 * lane);
            const ulonglong2* wp = reinterpret_cast<const ulonglong2*>(wbase + k * 128);
            ulonglong2 wA = wp[0], wB = wp[1], wC = wp[2], wE = wp[3];
            fma2(acc[0][0], av.x, wA.x); fma2(acc[0][1], av.x, wA.y);
            fma2(acc[0][2], av.x, wB.x); fma2(acc[0][3], av.x, wB.y);
            fma2(acc[0][4], av.x, wC.x); fma2(acc[0][5], av.x, wC.y);
            fma2(acc[0][6], av.x, wE.x); fma2(acc[0][7], av.x, wE.y);
            fma2(acc[1][0], av.y, wA.x); fma2(acc[1][1], av.y, wA.y);
            fma2(acc[1][2], av.y, wB.x); fma2(acc[1][3], av.y, wB.y);
            fma2(acc[1][4], av.y, wC.x); fma2(acc[1][5], av.y, wC.y);
            fma2(acc[1][6], av.y, wE.x); fma2(acc[1][7], av.y, wE.y);
        }
    }

    __syncthreads();

    // ---- bias + relu; write hidden (duplicated) back into sA; load W2 ----
    #pragma unroll
    for (int cp = 0; cp < 8; cp++) {
        int c0 = wc + 2 * cp, c1 = c0 + 1;
        float2 h0 = unpk(acc[0][cp]);
        float2 h1 = unpk(acc[1][cp]);
        float bc0 = b1[c0], bc1 = b1[c1];
        float v00 = fmaxf(h0.x + bc0, 0.f), v01 = fmaxf(h0.y + bc1, 0.f);
        float v10 = fmaxf(h1.x + bc0, 0.f), v11 = fmaxf(h1.y + bc1, 0.f);
        *(unsigned long long*)(sA + c0 * AROW + 4 * lane)     = pk(v00, v00);
        *(unsigned long long*)(sA + c0 * AROW + 4 * lane + 2) = pk(v10, v10);
        *(unsigned long long*)(sA + c1 * AROW + 4 * lane)     = pk(v01, v01);
        *(unsigned long long*)(sA + c1 * AROW + 4 * lane + 2) = pk(v11, v11);
    }
    {
        const float4* src = reinterpret_cast<const float4*>(W2);
        float4* dst = reinterpret_cast<float4*>(sW);
        #pragma unroll
        for (int i = tid; i < (128 * 128) / 4; i += THREADS) dst[i] = src[i];
    }
    __syncthreads();

    // ---- GEMM2: out = H @ W2 + b2 ----
    #pragma unroll
    for (int a = 0; a < 2; a++)
        #pragma unroll
        for (int c = 0; c < 8; c++) acc[a][c] = 0ull;

    #pragma unroll 8
    for (int k = 0; k < 128; k++) {
        ulonglong2 av = *reinterpret_cast<const ulonglong2*>(sA + k * AROW + 4 * lane);
        const ulonglong2* wp = reinterpret_cast<const ulonglong2*>(sW + k * 128 + wc);
        ulonglong2 wA = wp[0], wB = wp[1], wC = wp[2], wE = wp[3];
        fma2(acc[0][0], av.x, wA.x); fma2(acc[0][1], av.x, wA.y);
        fma2(acc[0][2], av.x, wB.x); fma2(acc[0][3], av.x, wB.y);
        fma2(acc[0][4], av.x, wC.x); fma2(acc[0][5], av.x, wC.y);
        fma2(acc[0][6], av.x, wE.x); fma2(acc[0][7], av.x, wE.y);
        fma2(acc[1][0], av.y, wA.x); fma2(acc[1][1], av.y, wA.y);
        fma2(acc[1][2], av.y, wB.x); fma2(acc[1][3], av.y, wB.y);
        fma2(acc[1][4], av.y, wC.x); fma2(acc[1][5], av.y, wC.y);
        fma2(acc[1][6], av.y, wE.x); fma2(acc[1][7], av.y, wE.y);
    }

    // ---- bias + store ----
    float o[2][16];
    #pragma unroll
    for (int cp = 0; cp < 8; cp++) {
        int c0 = wc + 2 * cp, c1 = c0 + 1;
        float2 p0 = unpk(acc[0][cp]);
        float2 p1 = unpk(acc[1][cp]);
        float bc0 = b2[c0], bc1 = b2[c1];
        o[0][2 * cp]     = p0.x + bc0;
        o[0][2 * cp + 1] = p0.y + bc1;
        o[1][2 * cp]     = p1.x + bc0;
        o[1][2 * cp + 1] = p1.y + bc1;
    }
    #pragma unroll
    for (int q = 0; q < 2; q++) {
        int node = base + n0 + q;
        if (node < nNodes) {
            float* dst = out + (size_t)node * D + wc;
            #pragma unroll
            for (int t = 0; t < 4; t++) {
                float4 v = make_float4(o[q][4 * t], o[q][4 * t + 1],
                                       o[q][4 * t + 2], o[q][4 * t + 3]);
                *reinterpret_cast<float4*>(dst + 4 * t) = v;
            }
        }
    }
}

// ---------------------------------------------------------------------------
extern "C" void kernel_launch(void* const* d_in, const int* in_sizes, int n_in,
                              void* d_out, int out_size) {
    const float* x         = (const float*)d_in[0];
    const float* edge_attr = (const float*)d_in[1];
    const int*   recv      = (const int*)d_in[2];
    const float* W1        = (const float*)d_in[3];
    const float* b1        = (const float*)d_in[4];
    const float* W2        = (const float*)d_in[5];
    const float* b2        = (const float*)d_in[6];
    float* out = (float*)d_out;

    int nNodes = in_sizes[0] / D;
    int E      = in_sizes[2];

    cudaFuncSetAttribute(mlp_kernel, cudaFuncAttributeMaxDynamicSharedMemorySize,
                         SMEM_BYTES);

    // CSR build
    zero_cnt_kernel<<<(nNodes + 255) / 256, 256>>>(nNodes);
    hist_kernel<<<(E + 255) / 256, 256>>>(recv, E);
    scan_kernel<<<1, 1024>>>(nNodes, E);
    fill_kernel<<<(E + 255) / 256, 256>>>(recv, E);

    // gather-reduce into g_agg (one warp per node, high occupancy)
    int gblocks = (nNodes * 32 + 255) / 256;
    gather_kernel<<<gblocks, 256>>>(edge_attr, nNodes);

    // fused MLP (packed f32x2)
    int tiles = (nNodes + TM - 1) / TM;
    mlp_kernel<<<tiles, THREADS, SMEM_BYTES>>>(x, W1, b1, W2, b2, out, nNodes);
}

// round 15
// speedup vs baseline: 1.2650x; 1.0581x over previous
#include <cuda_runtime.h>
#include <cstdint>

#define D 128
#define TM 64
#define THREADS 256
#define AROW 132                        // floats per k-row of dup'd activation tile (128 dup + 4 pad)
#define SA_F (128 * AROW)               // 16896 floats = 67,584 B
#define SMEM_BYTES (SA_F * 4)

// Scratch for the scatter-add aggregate (25.6 MB). Static __device__ array per rules.
__device__ float g_agg[50000 * D];

// ---------------------------------------------------------------------------
__global__ void zero_agg_kernel(int n4) {
    int i = blockIdx.x * blockDim.x + threadIdx.x;
    if (i < n4) {
        float4 z = {0.f, 0.f, 0.f, 0.f};
        reinterpret_cast<float4*>(g_agg)[i] = z;
    }
}

// One thread per (edge, 4-column group): coalesced 16B load, ONE vectorized
// red.global.add.v4.f32. g_agg is L2-resident (25.6MB < 126MB). This was the
// cheapest aggregation across R5/R8/R10/R14 experiments (LTS-reduce bound).
__global__ void scatter_kernel(const float* __restrict__ edge_attr,
                               const int* __restrict__ recv, int E) {
    long long i = (long long)blockIdx.x * blockDim.x + threadIdx.x;
    if (i >= (long long)E * (D / 4)) return;
    int e  = (int)(i >> 5);
    int c4 = ((int)i & 31) << 2;
    float4 v = reinterpret_cast<const float4*>(edge_attr + (size_t)e * D)[c4 >> 2];
    int r = recv[e];
    float* dst = g_agg + (size_t)r * D + c4;
    asm volatile("red.global.add.v4.f32 [%0], {%1, %2, %3, %4};"
                 :: "l"(dst), "f"(v.x), "f"(v.y), "f"(v.z), "f"(v.w)
                 : "memory");
}

// ---------------------------------------------------------------------------
// Packed-f32x2 helpers (sm_100+). Exact fp32 math, 2 FMAs per instruction.
__device__ __forceinline__ void fma2(unsigned long long& d,
                                     unsigned long long a, unsigned long long b) {
    asm("fma.rn.f32x2 %0, %1, %2, %0;" : "+l"(d) : "l"(a), "l"(b));
}
__device__ __forceinline__ float2 unpk(unsigned long long p) {
    float2 r;
    asm("mov.b64 {%0, %1}, %2;" : "=f"(r.x), "=f"(r.y) : "l"(p));
    return r;
}
__device__ __forceinline__ unsigned long long pk(float lo, float hi) {
    unsigned long long p;
    asm("mov.b64 %0, {%1, %2};" : "=l"(p) : "f"(lo), "f"(hi));
    return p;
}

// ---------------------------------------------------------------------------
// Fused MLP, packed-f32x2, smem = activation tile ONLY (67.6KB) -> 2 CTAs/SM,
// 16 warps/SM for latency hiding. Weights read via warp-uniform broadcast LDG
// (W1 128KB + W2 64KB, identical across all CTAs -> L1/L2 resident).
__global__ __launch_bounds__(THREADS, 2)
void mlp_kernel(const float* __restrict__ x,
                const float* __restrict__ W1, const float* __restrict__ b1,
                const float* __restrict__ W2, const float* __restrict__ b2,
                float* __restrict__ out, int nNodes) {
    extern __shared__ float sA[];        // [128][AROW] dup'd activations (reused as hidden)

    const int tid  = threadIdx.x;
    const int lane = tid & 31;
    const int warp = tid >> 5;
    const int wc   = warp * 16;            // warp's output-column base
    const int base = blockIdx.x * TM;
    const int n0   = 2 * lane;             // thread's two tile-local nodes

    unsigned long long acc[2][8];
    #pragma unroll
    for (int a = 0; a < 2; a++)
        #pragma unroll
        for (int c = 0; c < 8; c++) acc[a][c] = 0ull;

    // ---- GEMM1 in two k-phases: K 0..127 = x, K 128..255 = g_agg ----
    for (int phase = 0; phase < 2; phase++) {
        const float* src = (phase == 0) ? x : g_agg;
        if (phase == 1) __syncthreads();   // all warps done reading previous sA

        // fill sA: node n's value at k goes (duplicated) to sA[k*AROW + 2n]
        for (int i = tid; i < TM * 32; i += THREADS) {
            int n  = i & 63;               // lanes differ in n -> contiguous STS.64
            int k4 = i >> 6;
            int node = base + n;
            float4 v = {0.f, 0.f, 0.f, 0.f};
            if (node < nNodes)
                v = reinterpret_cast<const float4*>(src + (size_t)node * D)[k4];
            *(unsigned long long*)(sA + (4 * k4 + 0) * AROW + 2 * n) = pk(v.x, v.x);
            *(unsigned long long*)(sA + (4 * k4 + 1) * AROW + 2 * n) = pk(v.y, v.y);
            *(unsigned long long*)(sA + (4 * k4 + 2) * AROW + 2 * n) = pk(v.z, v.z);
            *(unsigned long long*)(sA + (4 * k4 + 3) * AROW + 2 * n) = pk(v.w, v.w);
        }
        __syncthreads();

        // weights straight from global: warp-uniform LDG.128 (broadcast)
        const float* wbase = W1 + (size_t)phase * 128 * 128 + wc;
        #pragma unroll 8
        for (int k = 0; k < 128; k++) {
            ulonglong2 av = *reinterpret_cast<const ulonglong2*>(sA + k * AROW + 4 * lane);
            const ulonglong2* wp = reinterpret_cast<const ulonglong2*>(wbase + (size_t)k * 128);
            ulonglong2 wA = wp[0], wB = wp[1], wC = wp[2], wE = wp[3];
            fma2(acc[0][0], av.x, wA.x); fma2(acc[0][1], av.x, wA.y);
            fma2(acc[0][2], av.x, wB.x); fma2(acc[0][3], av.x, wB.y);
            fma2(acc[0][4], av.x, wC.x); fma2(acc[0][5], av.x, wC.y);
            fma2(acc[0][6], av.x, wE.x); fma2(acc[0][7], av.x, wE.y);
            fma2(acc[1][0], av.y, wA.x); fma2(acc[1][1], av.y, wA.y);
            fma2(acc[1][2], av.y, wB.x); fma2(acc[1][3], av.y, wB.y);
            fma2(acc[1][4], av.y, wC.x); fma2(acc[1][5], av.y, wC.y);
            fma2(acc[1][6], av.y, wE.x); fma2(acc[1][7], av.y, wE.y);
        }
    }

    __syncthreads();   // GEMM1 reads of sA complete everywhere

    // ---- bias + relu; write hidden (duplicated) back into sA ----
    #pragma unroll
    for (int cp = 0; cp < 8; cp++) {
        int c0 = wc + 2 * cp, c1 = c0 + 1;
        float2 h0 = unpk(acc[0][cp]);      // node n0 : cols (c0, c1)
        float2 h1 = unpk(acc[1][cp]);      // node n0+1
        float bc0 = __ldg(b1 + c0), bc1 = __ldg(b1 + c1);
        float v00 = fmaxf(h0.x + bc0, 0.f), v01 = fmaxf(h0.y + bc1, 0.f);
        float v10 = fmaxf(h1.x + bc0, 0.f), v11 = fmaxf(h1.y + bc1, 0.f);
        *(unsigned long long*)(sA + c0 * AROW + 4 * lane)     = pk(v00, v00);
        *(unsigned long long*)(sA + c0 * AROW + 4 * lane + 2) = pk(v10, v10);
        *(unsigned long long*)(sA + c1 * AROW + 4 * lane)     = pk(v01, v01);
        *(unsigned long long*)(sA + c1 * AROW + 4 * lane + 2) = pk(v11, v11);
    }
    __syncthreads();

    // ---- GEMM2: out = H @ W2 + b2 ----
    #pragma unroll
    for (int a = 0; a < 2; a++)
        #pragma unroll
        for (int c = 0; c < 8; c++) acc[a][c] = 0ull;

    {
        const float* wbase = W2 + wc;
        #pragma unroll 8
        for (int k = 0; k < 128; k++) {
            ulonglong2 av = *reinterpret_cast<const ulonglong2*>(sA + k * AROW + 4 * lane);
            const ulonglong2* wp = reinterpret_cast<const ulonglong2*>(wbase + (size_t)k * 128);
            ulonglong2 wA = wp[0], wB = wp[1], wC = wp[2], wE = wp[3];
            fma2(acc[0][0], av.x, wA.x); fma2(acc[0][1], av.x, wA.y);
            fma2(acc[0][2], av.x, wB.x); fma2(acc[0][3], av.x, wB.y);
            fma2(acc[0][4], av.x, wC.x); fma2(acc[0][5], av.x, wC.y);
            fma2(acc[0][6], av.x, wE.x); fma2(acc[0][7], av.x, wE.y);
            fma2(acc[1][0], av.y, wA.x); fma2(acc[1][1], av.y, wA.y);
            fma2(acc[1][2], av.y, wB.x); fma2(acc[1][3], av.y, wB.y);
            fma2(acc[1][4], av.y, wC.x); fma2(acc[1][5], av.y, wC.y);
            fma2(acc[1][6], av.y, wE.x); fma2(acc[1][7], av.y, wE.y);
        }
    }

    // ---- bias + store ----
    float o[2][16];
    #pragma unroll
    for (int cp = 0; cp < 8; cp++) {
        int c0 = wc + 2 * cp, c1 = c0 + 1;
        float2 p0 = unpk(acc[0][cp]);
        float2 p1 = unpk(acc[1][cp]);
        float bc0 = __ldg(b2 + c0), bc1 = __ldg(b2 + c1);
        o[0][2 * cp]     = p0.x + bc0;
        o[0][2 * cp + 1] = p0.y + bc1;
        o[1][2 * cp]     = p1.x + bc0;
        o[1][2 * cp + 1] = p1.y + bc1;
    }
    #pragma unroll
    for (int q = 0; q < 2; q++) {
        int node = base + n0 + q;
        if (node < nNodes) {
            float* dst = out + (size_t)node * D + wc;
            #pragma unroll
            for (int t = 0; t < 4; t++) {
                float4 v = make_float4(o[q][4 * t], o[q][4 * t + 1],
                                       o[q][4 * t + 2], o[q][4 * t + 3]);
                *reinterpret_cast<float4*>(dst + 4 * t) = v;
            }
        }
    }
}

// ---------------------------------------------------------------------------
extern "C" void kernel_launch(void* const* d_in, const int* in_sizes, int n_in,
                              void* d_out, int out_size) {
    const float* x         = (const float*)d_in[0];
    const float* edge_attr = (const float*)d_in[1];
    const int*   recv      = (const int*)d_in[2];
    const float* W1        = (const float*)d_in[3];
    const float* b1        = (const float*)d_in[4];
    const float* W2        = (const float*)d_in[5];
    const float* b2        = (const float*)d_in[6];
    float* out = (float*)d_out;

    int nNodes = in_sizes[0] / D;
    int E      = in_sizes[2];

    cudaFuncSetAttribute(mlp_kernel, cudaFuncAttributeMaxDynamicSharedMemorySize,
                         SMEM_BYTES);

    // 1) zero aggregate
    int n4 = nNodes * D / 4;
    zero_agg_kernel<<<(n4 + 255) / 256, 256>>>(n4);

    // 2) scatter-add edge features (vectorized v4 reductions)
    long long threads = (long long)E * (D / 4);
    int sblocks = (int)((threads + 255) / 256);
    scatter_kernel<<<sblocks, 256>>>(edge_attr, recv, E);

    // 3) fused MLP (packed f32x2, 2 CTAs/SM)
    int tiles = (nNodes + TM - 1) / TM;
    mlp_kernel<<<tiles, THREADS, SMEM_BYTES>>>(x, W1, b1, W2, b2, out, nNodes);
}

// round 16
// speedup vs baseline: 1.6370x; 1.2941x over previous
#include <cuda_runtime.h>
#include <cstdint>

#define D 128
#define TM 128                          // nodes per CTA
#define THREADS 256
#define ARO 260                         // words per k-row of dup'd tile (2*TM + 4 pad)
#define SA_F (128 * ARO)                // 33,280 floats = 133,120 B
#define SW_F (128 * 128)                // one 64KB weight half
#define SMEM_BYTES ((SA_F + SW_F) * 4)  // 198,656 B

// Scratch for the scatter-add aggregate (25.6 MB). Static __device__ array per rules.
__device__ float g_agg[50000 * D];

// ---------------------------------------------------------------------------
__global__ void zero_agg_kernel(int n4) {
    int i = blockIdx.x * blockDim.x + threadIdx.x;
    if (i < n4) {
        float4 z = {0.f, 0.f, 0.f, 0.f};
        reinterpret_cast<float4*>(g_agg)[i] = z;
    }
}

// One thread per (edge, 4-column group): coalesced 16B load, ONE vectorized
// red.global.add.v4.f32. g_agg is L2-resident. Best aggregation across
// R5/R8/R10/R14 experiments (LTS-reduce bound, ~100us).
__global__ void scatter_kernel(const float* __restrict__ edge_attr,
                               const int* __restrict__ recv, int E) {
    long long i = (long long)blockIdx.x * blockDim.x + threadIdx.x;
    if (i >= (long long)E * (D / 4)) return;
    int e  = (int)(i >> 5);
    int c4 = ((int)i & 31) << 2;
    float4 v = reinterpret_cast<const float4*>(edge_attr + (size_t)e * D)[c4 >> 2];
    int r = recv[e];
    float* dst = g_agg + (size_t)r * D + c4;
    asm volatile("red.global.add.v4.f32 [%0], {%1, %2, %3, %4};"
                 :: "l"(dst), "f"(v.x), "f"(v.y), "f"(v.z), "f"(v.w)
                 : "memory");
}

// ---------------------------------------------------------------------------
// Packed-f32x2 helpers (sm_100+). Exact fp32 math, 2 FMAs per instruction.
__device__ __forceinline__ void fma2(unsigned long long& d,
                                     unsigned long long a, unsigned long long b) {
    asm("fma.rn.f32x2 %0, %1, %2, %0;" : "+l"(d) : "l"(a), "l"(b));
}
__device__ __forceinline__ float2 unpk(unsigned long long p) {
    float2 r;
    asm("mov.b64 {%0, %1}, %2;" : "=f"(r.x), "=f"(r.y) : "l"(p));
    return r;
}
__device__ __forceinline__ unsigned long long pk(float lo, float hi) {
    unsigned long long p;
    asm("mov.b64 %0, {%1, %2};" : "=l"(p) : "f"(lo), "f"(hi));
    return p;
}

// ---------------------------------------------------------------------------
// Fused MLP, packed-f32x2, TM=128 nodes/CTA, 4-node x 16-col thread tile.
//   Warp w: output cols [16w,16w+16). Lane l: tile nodes 4l..4l+3.
//   sA[k][ARO]: dup'd activations; lane l reads 32B (2x LDS.128) per k.
//   sW: streamed weight halves (W1 rows 0-127, then 128-255, then W2) - smem
//   broadcast for weights (proven faster than LDG in R15).
//   Inner loop per warp per k: 2 a-LDS.128 + 4 w-LDS.128 + 32 FFMA2
//   -> 12 smem wavefronts per 32 FFMA2 -> FMA-pipe bound (128 cyc/k/SM vs 96).
__global__ __launch_bounds__(THREADS, 1)
void mlp_kernel(const float* __restrict__ x,
                const float* __restrict__ W1, const float* __restrict__ b1,
                const float* __restrict__ W2, const float* __restrict__ b2,
                float* __restrict__ out, int nNodes) {
    extern __shared__ float smem[];
    float* sA = smem;            // [128][ARO] dup'd activations (reused as hidden)
    float* sW = smem + SA_F;     // current 128x128 weight block

    const int tid  = threadIdx.x;
    const int lane = tid & 31;
    const int warp = tid >> 5;
    const int wc   = warp * 16;            // warp's output-column base
    const int base = blockIdx.x * TM;
    const int n0   = 4 * lane;             // thread's four tile-local nodes

    unsigned long long acc[4][8];
    #pragma unroll
    for (int a = 0; a < 4; a++)
        #pragma unroll
        for (int c = 0; c < 8; c++) acc[a][c] = 0ull;

    // ---- GEMM1 in two k-phases: K 0..127 = x, K 128..255 = g_agg ----
    for (int phase = 0; phase < 2; phase++) {
        const float* src = (phase == 0) ? x : g_agg;
        if (phase == 1) __syncthreads();   // previous sA/sW reads complete

        // stage this phase's W1 half (64KB), coalesced float4
        {
            const float4* wsrc = reinterpret_cast<const float4*>(W1 + (size_t)phase * 128 * 128);
            float4* wdst = reinterpret_cast<float4*>(sW);
            #pragma unroll
            for (int i = tid; i < SW_F / 4; i += THREADS) wdst[i] = wsrc[i];
        }

        // fill sA: node n's value at k goes (duplicated) to sA[k*ARO + 2n]
        for (int i = tid; i < TM * 32; i += THREADS) {
            int n  = i & 127;              // lanes differ in n -> conflict-free STS.64
            int k4 = i >> 7;
            int node = base + n;
            float4 v = {0.f, 0.f, 0.f, 0.f};
            if (node < nNodes)
                v = reinterpret_cast<const float4*>(src + (size_t)node * D)[k4];
            *(unsigned long long*)(sA + (4 * k4 + 0) * ARO + 2 * n) = pk(v.x, v.x);
            *(unsigned long long*)(sA + (4 * k4 + 1) * ARO + 2 * n) = pk(v.y, v.y);
            *(unsigned long long*)(sA + (4 * k4 + 2) * ARO + 2 * n) = pk(v.z, v.z);
            *(unsigned long long*)(sA + (4 * k4 + 3) * ARO + 2 * n) = pk(v.w, v.w);
        }
        __syncthreads();

        #pragma unroll 4
        for (int k = 0; k < 128; k++) {
            const float* arow = sA + k * ARO + 8 * lane;
            ulonglong2 av0 = *reinterpret_cast<const ulonglong2*>(arow);      // nodes 4l,4l+1
            ulonglong2 av1 = *reinterpret_cast<const ulonglong2*>(arow + 4);  // nodes 4l+2,4l+3
            const ulonglong2* wp = reinterpret_cast<const ulonglong2*>(sW + k * 128 + wc);
            ulonglong2 wA = wp[0], wB = wp[1], wC = wp[2], wE = wp[3];
            fma2(acc[0][0], av0.x, wA.x); fma2(acc[0][1], av0.x, wA.y);
            fma2(acc[0][2], av0.x, wB.x); fma2(acc[0][3], av0.x, wB.y);
            fma2(acc[0][4], av0.x, wC.x); fma2(acc[0][5], av0.x, wC.y);
            fma2(acc[0][6], av0.x, wE.x); fma2(acc[0][7], av0.x, wE.y);
            fma2(acc[1][0], av0.y, wA.x); fma2(acc[1][1], av0.y, wA.y);
            fma2(acc[1][2], av0.y, wB.x); fma2(acc[1][3], av0.y, wB.y);
            fma2(acc[1][4], av0.y, wC.x); fma2(acc[1][5], av0.y, wC.y);
            fma2(acc[1][6], av0.y, wE.x); fma2(acc[1][7], av0.y, wE.y);
            fma2(acc[2][0], av1.x, wA.x); fma2(acc[2][1], av1.x, wA.y);
            fma2(acc[2][2], av1.x, wB.x); fma2(acc[2][3], av1.x, wB.y);
            fma2(acc[2][4], av1.x, wC.x); fma2(acc[2][5], av1.x, wC.y);
            fma2(acc[2][6], av1.x, wE.x); fma2(acc[2][7], av1.x, wE.y);
            fma2(acc[3][0], av1.y, wA.x); fma2(acc[3][1], av1.y, wA.y);
            fma2(acc[3][2], av1.y, wB.x); fma2(acc[3][3], av1.y, wB.y);
            fma2(acc[3][4], av1.y, wC.x); fma2(acc[3][5], av1.y, wC.y);
            fma2(acc[3][6], av1.y, wE.x); fma2(acc[3][7], av1.y, wE.y);
        }
    }

    __syncthreads();   // GEMM1 reads of sA and sW complete everywhere

    // ---- bias + relu; write hidden (duplicated) back into sA; stage W2 ----
    #pragma unroll
    for (int cp = 0; cp < 8; cp++) {
        int c0 = wc + 2 * cp, c1 = c0 + 1;
        float bc0 = __ldg(b1 + c0), bc1 = __ldg(b1 + c1);
        #pragma unroll
        for (int q = 0; q < 4; q++) {
            float2 h = unpk(acc[q][cp]);
            float v0 = fmaxf(h.x + bc0, 0.f);
            float v1 = fmaxf(h.y + bc1, 0.f);
            *(unsigned long long*)(sA + c0 * ARO + 2 * (n0 + q)) = pk(v0, v0);
            *(unsigned long long*)(sA + c1 * ARO + 2 * (n0 + q)) = pk(v1, v1);
        }
    }
    {
        const float4* wsrc = reinterpret_cast<const float4*>(W2);
        float4* wdst = reinterpret_cast<float4*>(sW);
        #pragma unroll
        for (int i = tid; i < SW_F / 4; i += THREADS) wdst[i] = wsrc[i];
    }
    __syncthreads();

    // ---- GEMM2: out = H @ W2 + b2 ----
    #pragma unroll
    for (int a = 0; a < 4; a++)
        #pragma unroll
        for (int c = 0; c < 8; c++) acc[a][c] = 0ull;

    #pragma unroll 4
    for (int k = 0; k < 128; k++) {
        const float* arow = sA + k * ARO + 8 * lane;
        ulonglong2 av0 = *reinterpret_cast<const ulonglong2*>(arow);
        ulonglong2 av1 = *reinterpret_cast<const ulonglong2*>(arow + 4);
        const ulonglong2* wp = reinterpret_cast<const ulonglong2*>(sW + k * 128 + wc);
        ulonglong2 wA = wp[0], wB = wp[1], wC = wp[2], wE = wp[3];
        fma2(acc[0][0], av0.x, wA.x); fma2(acc[0][1], av0.x, wA.y);
        fma2(acc[0][2], av0.x, wB.x); fma2(acc[0][3], av0.x, wB.y);
        fma2(acc[0][4], av0.x, wC.x); fma2(acc[0][5], av0.x, wC.y);
        fma2(acc[0][6], av0.x, wE.x); fma2(acc[0][7], av0.x, wE.y);
        fma2(acc[1][0], av0.y, wA.x); fma2(acc[1][1], av0.y, wA.y);
        fma2(acc[1][2], av0.y, wB.x); fma2(acc[1][3], av0.y, wB.y);
        fma2(acc[1][4], av0.y, wC.x); fma2(acc[1][5], av0.y, wC.y);
        fma2(acc[1][6], av0.y, wE.x); fma2(acc[1][7], av0.y, wE.y);
        fma2(acc[2][0], av1.x, wA.x); fma2(acc[2][1], av1.x, wA.y);
        fma2(acc[2][2], av1.x, wB.x); fma2(acc[2][3], av1.x, wB.y);
        fma2(acc[2][4], av1.x, wC.x); fma2(acc[2][5], av1.x, wC.y);
        fma2(acc[2][6], av1.x, wE.x); fma2(acc[2][7], av1.x, wE.y);
        fma2(acc[3][0], av1.y, wA.x); fma2(acc[3][1], av1.y, wA.y);
        fma2(acc[3][2], av1.y, wB.x); fma2(acc[3][3], av1.y, wB.y);
        fma2(acc[3][4], av1.y, wC.x); fma2(acc[3][5], av1.y, wC.y);
        fma2(acc[3][6], av1.y, wE.x); fma2(acc[3][7], av1.y, wE.y);
    }

    // ---- bias + store ----
    #pragma unroll
    for (int q = 0; q < 4; q++) {
        int node = base + n0 + q;
        if (node < nNodes) {
            float o[16];
            #pragma unroll
            for (int cp = 0; cp < 8; cp++) {
                float2 p = unpk(acc[q][cp]);
                o[2 * cp]     = p.x + __ldg(b2 + wc + 2 * cp);
                o[2 * cp + 1] = p.y + __ldg(b2 + wc + 2 * cp + 1);
            }
            float* dst = out + (size_t)node * D + wc;
            #pragma unroll
            for (int t = 0; t < 4; t++) {
                float4 v = make_float4(o[4 * t], o[4 * t + 1],
                                       o[4 * t + 2], o[4 * t + 3]);
                *reinterpret_cast<float4*>(dst + 4 * t) = v;
            }
        }
    }
}

// ---------------------------------------------------------------------------
extern "C" void kernel_launch(void* const* d_in, const int* in_sizes, int n_in,
                              void* d_out, int out_size) {
    const float* x         = (const float*)d_in[0];
    const float* edge_attr = (const float*)d_in[1];
    const int*   recv      = (const int*)d_in[2];
    const float* W1        = (const float*)d_in[3];
    const float* b1        = (const float*)d_in[4];
    const float* W2        = (const float*)d_in[5];
    const float* b2        = (const float*)d_in[6];
    float* out = (float*)d_out;

    int nNodes = in_sizes[0] / D;
    int E      = in_sizes[2];

    cudaFuncSetAttribute(mlp_kernel, cudaFuncAttributeMaxDynamicSharedMemorySize,
                         SMEM_BYTES);

    // 1) zero aggregate
    int n4 = nNodes * D / 4;
    zero_agg_kernel<<<(n4 + 255) / 256, 256>>>(n4);

    // 2) scatter-add edge features (vectorized v4 reductions)
    long long threads = (long long)E * (D / 4);
    int sblocks = (int)((threads + 255) / 256);
    scatter_kernel<<<sblocks, 256>>>(edge_attr, recv, E);

    // 3) fused MLP (packed f32x2, TM=128, streamed weight halves in smem)
    int tiles = (nNodes + TM - 1) / TM;
    mlp_kernel<<<tiles, THREADS, SMEM_BYTES>>>(x, W1, b1, W2, b2, out, nNodes);
}